// round 1
// baseline (speedup 1.0000x reference)
#include <cuda_runtime.h>

// RNN-T joint network:
//   enc_proj[bt, v]  = enc[bt, :512]  . W[v, 0:512]
//   pred_proj[bu, v] = pred[bu, :512] . W[v, 512:1024]
//   out[b,t,u,v] = enc_proj[b*T+t, v] + pred_proj[b*U+u, v] + bias[v]
// Shapes: B=4, T=256, U=64, D=512(+512), V=2048. Output = 134M fp32 = 512 MiB.
//
// Stage 1: fused GEMM kernel (both projections, one grid) using packed
//          fma.rn.f32x2 (Blackwell FFMA2, 2x the fp32 FFMA issue rate).
// Stage 2: broadcast-add kernel, DRAM-write-bound (~536 MB of stores).

#define VOCAB 2048
#define DK    512
#define WLD   1024
#define NB    4
#define NT    256
#define NU    64

// Scratch (allocation-free rule: device globals)
__device__ float g_enc [NB * NT * VOCAB];   // 1024 x 2048 (8 MB)
__device__ float g_pred[NB * NU * VOCAB];   //  256 x 2048 (2 MB)

typedef unsigned long long u64;

__device__ __forceinline__ u64 pk2(float lo, float hi) {
    u64 r;
    asm("mov.b64 %0, {%1, %2};" : "=l"(r) : "f"(lo), "f"(hi));
    return r;
}
__device__ __forceinline__ void fma2(u64& d, u64 a, u64 b) {
    asm("fma.rn.f32x2 %0, %1, %2, %0;" : "+l"(d) : "l"(a), "l"(b));
}

// ---------------------------------------------------------------------------
// GEMM: C[m, v] = sum_k A[m, k] * W[v, off + k]
// Tiles: BM=64, BN=128, BK=16. 256 threads, each computes 4(M) x 8(N) as
// 4x4 f32x2 accumulators (pairs along N). Grid y: tiles 0..15 = enc (M=1024),
// tiles 16..19 = pred (M=256). 16 N-tiles -> 320 blocks total.
// ---------------------------------------------------------------------------
__global__ __launch_bounds__(256)
void gemm_kernel(const float* __restrict__ enc,
                 const float* __restrict__ pred,
                 const float* __restrict__ W) {
    __shared__ float As[16 * 76];    // padded rows: 76 floats (16B-aligned rows)
    __shared__ float Bs[16 * 132];   // padded rows: 132 floats

    const int tid   = threadIdx.x;
    const int vbase = blockIdx.x * 128;
    const int my    = blockIdx.y;

    const float* A;
    float*       C;
    int off, Mbase;
    if (my < 16) { A = enc;  C = g_enc;  off = 0;   Mbase = my * 64; }
    else         { A = pred; C = g_pred; off = DK;  Mbase = (my - 16) * 64; }

    const int r  = tid >> 2;          // 0..63
    const int c4 = (tid & 3) * 4;     // 0,4,8,12
    const int tx = tid & 15;          // N: tx*8
    const int ty = tid >> 4;          // M: ty*4

    const float* Aptr = A + (Mbase + r) * DK + c4;
    const float* Wp0  = W + (size_t)(vbase + r)      * WLD + off + c4;
    const float* Wp1  = W + (size_t)(vbase + r + 64) * WLD + off + c4;

    // prefetch first tile
    float4 a0 = *(const float4*)(Aptr);
    float4 b0 = *(const float4*)(Wp0);
    float4 b1 = *(const float4*)(Wp1);

    u64 acc[4][4] = {};

    for (int kt = 0; kt < DK; kt += 16) {
        __syncthreads();
        // store A tile transposed: As[k][m]
        As[(c4 + 0) * 76 + r] = a0.x;
        As[(c4 + 1) * 76 + r] = a0.y;
        As[(c4 + 2) * 76 + r] = a0.z;
        As[(c4 + 3) * 76 + r] = a0.w;
        // store B tile transposed: Bs[k][v]
        Bs[(c4 + 0) * 132 + r]      = b0.x;
        Bs[(c4 + 1) * 132 + r]      = b0.y;
        Bs[(c4 + 2) * 132 + r]      = b0.z;
        Bs[(c4 + 3) * 132 + r]      = b0.w;
        Bs[(c4 + 0) * 132 + r + 64] = b1.x;
        Bs[(c4 + 1) * 132 + r + 64] = b1.y;
        Bs[(c4 + 2) * 132 + r + 64] = b1.z;
        Bs[(c4 + 3) * 132 + r + 64] = b1.w;
        __syncthreads();

        // prefetch next tile while computing on this one
        if (kt + 16 < DK) {
            a0 = *(const float4*)(Aptr + kt + 16);
            b0 = *(const float4*)(Wp0 + kt + 16);
            b1 = *(const float4*)(Wp1 + kt + 16);
        }

        #pragma unroll
        for (int kk = 0; kk < 16; kk++) {
            float4 av = *(const float4*)&As[kk * 76 + ty * 4];
            const u64* bp = (const u64*)&Bs[kk * 132 + tx * 8];
            u64 bb0 = bp[0], bb1 = bp[1], bb2 = bp[2], bb3 = bp[3];
            float aa[4] = {av.x, av.y, av.z, av.w};
            #pragma unroll
            for (int i = 0; i < 4; i++) {
                u64 ap = pk2(aa[i], aa[i]);
                fma2(acc[i][0], ap, bb0);
                fma2(acc[i][1], ap, bb1);
                fma2(acc[i][2], ap, bb2);
                fma2(acc[i][3], ap, bb3);
            }
        }
    }

    #pragma unroll
    for (int i = 0; i < 4; i++) {
        u64* cp = (u64*)&C[(size_t)(Mbase + ty * 4 + i) * VOCAB + vbase + tx * 8];
        #pragma unroll
        for (int j = 0; j < 4; j++) cp[j] = acc[i][j];
    }
}

// ---------------------------------------------------------------------------
// Broadcast add: one block per (b, t). enc_row + bias hoisted into registers;
// loop over u reads pred rows (L2-resident, 2 MB total) and streams 512 KB of
// coalesced float4 stores per block. DRAM-write-bound by design.
// ---------------------------------------------------------------------------
__global__ __launch_bounds__(256)
void add_kernel(const float* __restrict__ bias, float* __restrict__ out) {
    const int bt  = blockIdx.x;        // 0..1023 == b*T + t
    const int b   = bt >> 8;           // T = 256
    const int tid = threadIdx.x;

    const float4* er = (const float4*)(g_enc + (size_t)bt * VOCAB);
    const float4* bi = (const float4*)bias;

    float4 ea = er[tid];
    float4 eb = er[tid + 256];
    float4 ba = bi[tid];
    float4 bb = bi[tid + 256];
    const float4 e0 = make_float4(ea.x + ba.x, ea.y + ba.y, ea.z + ba.z, ea.w + ba.w);
    const float4 e1 = make_float4(eb.x + bb.x, eb.y + bb.y, eb.z + bb.z, eb.w + bb.w);

    const float4* pr = (const float4*)(g_pred + (size_t)b * NU * VOCAB);
    float4* o = (float4*)(out + (size_t)bt * NU * VOCAB);

    #pragma unroll 4
    for (int u = 0; u < NU; u++) {
        float4 p0 = pr[u * 512 + tid];
        float4 p1 = pr[u * 512 + tid + 256];
        o[u * 512 + tid] =
            make_float4(e0.x + p0.x, e0.y + p0.y, e0.z + p0.z, e0.w + p0.w);
        o[u * 512 + tid + 256] =
            make_float4(e1.x + p1.x, e1.y + p1.y, e1.z + p1.z, e1.w + p1.w);
    }
}

extern "C" void kernel_launch(void* const* d_in, const int* in_sizes, int n_in,
                              void* d_out, int out_size) {
    const float* enc  = (const float*)d_in[0];   // (4, 256, 512) f32
    const float* pred = (const float*)d_in[1];   // (4, 64, 512)  f32
    const float* W    = (const float*)d_in[2];   // (2048, 1024)  f32
    const float* bias = (const float*)d_in[3];   // (2048,)       f32
    float* out = (float*)d_out;                  // (4,256,64,2048) f32

    dim3 gemm_grid(16, 20);   // 16 N-tiles x (16 enc + 4 pred) M-tiles
    gemm_kernel<<<gemm_grid, 256>>>(enc, pred, W);
    add_kernel<<<NB * NT, 256>>>(bias, out);
}

// round 2
// speedup vs baseline: 1.6914x; 1.6914x over previous
#include <cuda_runtime.h>
#include <cuda_bf16.h>
#include <cstdint>

// RNN-T joint network, 3 stages:
//  1) convert: fp32 -> bf16 (hi,lo) split images
//       Ac[m][1536]  = [A_hi | A_hi | A_lo]     (rows 0..1023 enc, 1024..1279 pred)
//       Be/Bp[v][1536] = [W_hi | W_lo | W_hi]   (enc half / pred half of W)
//     => single K=1536 bf16 GEMM == hi*hi + hi*lo + lo*hi  (fp32-grade accuracy)
//  2) gemm: tensor-core mma.sync.m16n8k16.bf16, 128x128 tiles, K=1536,
//     cp.async double-buffered, writes fp32 projections to scratch.
//  3) add: broadcast add. pred+bias chunk cached in SMEM (kills the 512MB of
//     L2 reads from round 1), streaming stores (st.global.cs).

#define VOCAB 2048
#define KC    1536
#define NB    4
#define NT    256
#define NU    64

// -------- scratch (device globals; no allocations allowed) --------
__device__ __nv_bfloat16 g_Ac[1280 * KC];   // 3.93 MB
__device__ __nv_bfloat16 g_Be[VOCAB * KC];  // 6.29 MB
__device__ __nv_bfloat16 g_Bp[VOCAB * KC];  // 6.29 MB
__device__ float g_enc [1024 * VOCAB];      // 8 MB
__device__ float g_pred[ 256 * VOCAB];      // 2 MB

// ---------------------------------------------------------------------------
// Stage 1: split-precision convert.  Each thread handles one float2 pair.
// segments (pair indices): enc [0,262144)  pred [262144,327680)  W [327680,1376256)
// ---------------------------------------------------------------------------
__global__ __launch_bounds__(256)
void convert_kernel(const float* __restrict__ enc,
                    const float* __restrict__ pred,
                    const float* __restrict__ W) {
    int idx = blockIdx.x * 256 + threadIdx.x;

    float2 x;
    __nv_bfloat16* base;
    bool isA;
    if (idx < 262144) {                       // enc
        x = ((const float2*)enc)[idx];
        int m = idx >> 8, k = (idx & 255) * 2;
        base = g_Ac + (size_t)m * KC + k;
        isA = true;
    } else if (idx < 327680) {                // pred
        int p = idx - 262144;
        x = ((const float2*)pred)[p];
        int m = 1024 + (p >> 8), k = (p & 255) * 2;
        base = g_Ac + (size_t)m * KC + k;
        isA = true;
    } else {                                  // W
        int p = idx - 327680;
        x = ((const float2*)W)[p];
        int v = p >> 9, k = (p & 511) * 2;
        if (k < 512) base = g_Be + (size_t)v * KC + k;
        else         base = g_Bp + (size_t)v * KC + (k - 512);
        isA = false;
    }

    __nv_bfloat162 h, l;
    h.x = __float2bfloat16_rn(x.x);
    h.y = __float2bfloat16_rn(x.y);
    l.x = __float2bfloat16_rn(x.x - __bfloat162float(h.x));
    l.y = __float2bfloat16_rn(x.y - __bfloat162float(h.y));

    if (isA) {  // [hi | hi | lo]
        *(__nv_bfloat162*)(base)        = h;
        *(__nv_bfloat162*)(base +  512) = h;
        *(__nv_bfloat162*)(base + 1024) = l;
    } else {    // [hi | lo | hi]
        *(__nv_bfloat162*)(base)        = h;
        *(__nv_bfloat162*)(base +  512) = l;
        *(__nv_bfloat162*)(base + 1024) = h;
    }
}

// ---------------------------------------------------------------------------
// Stage 2: bf16 tensor-core GEMM.  C[m,v] = Ac[m,:] . B[v,:]  (K=1536)
// Block tile 128(M) x 128(N), BK=32, 8 warps in 2(M) x 4(N), warp tile 64x32.
// grid = (16 n-tiles, 10 m-tiles); m-tiles 0..7 -> enc, 8..9 -> pred.
// ---------------------------------------------------------------------------
#define SROW 40                 // padded SMEM row (halves): 80B stride, LDSM conflict-free
#define SBUF (128 * SROW * 2)   // bytes per buffer

__device__ __forceinline__ uint32_t s2u(const void* p) {
    return (uint32_t)__cvta_generic_to_shared(p);
}
#define CPA16(s, g) asm volatile("cp.async.cg.shared.global [%0], [%1], 16;" :: "r"(s), "l"(g))
#define LDSM4(r0,r1,r2,r3,a) asm volatile( \
    "ldmatrix.sync.aligned.m8n8.x4.shared.b16 {%0,%1,%2,%3}, [%4];" \
    : "=r"(r0),"=r"(r1),"=r"(r2),"=r"(r3) : "r"(a))
#define MMA16816(c,a0,a1,a2,a3,b0,b1) asm volatile( \
    "mma.sync.aligned.m16n8k16.row.col.f32.bf16.bf16.f32 " \
    "{%0,%1,%2,%3},{%4,%5,%6,%7},{%8,%9},{%0,%1,%2,%3};" \
    : "+f"(c[0]),"+f"(c[1]),"+f"(c[2]),"+f"(c[3]) \
    : "r"(a0),"r"(a1),"r"(a2),"r"(a3),"r"(b0),"r"(b1))

__global__ __launch_bounds__(256)
void gemm_kernel() {
    __shared__ __nv_bfloat16 As[2][128 * SROW];
    __shared__ __nv_bfloat16 Bs[2][128 * SROW];

    const int tid  = threadIdx.x;
    const int lane = tid & 31;
    const int wid  = tid >> 5;
    const int warp_m = wid & 1;     // 0..1  (64 M rows each)
    const int warp_n = wid >> 1;    // 0..3  (32 N cols each)

    const int my    = blockIdx.y;
    const int Mbase = my * 128;
    const int vbase = blockIdx.x * 128;

    const __nv_bfloat16* Bg = (my < 8) ? g_Be : g_Bp;
    float* C = (my < 8) ? (g_enc + (size_t)Mbase * VOCAB)
                        : (g_pred + (size_t)(Mbase - 1024) * VOCAB);

    // -------- cp.async staging: each thread copies 2x16B for A, 2x16B for B
    const int lrow = tid >> 2;            // 0..63
    const int lc   = (tid & 3) * 8;       // half offset (16B chunks)
    const __nv_bfloat16* ga = g_Ac + (size_t)(Mbase + lrow) * KC + lc;
    const __nv_bfloat16* gb = Bg   + (size_t)(vbase + lrow) * KC + lc;
    const uint32_t sa = s2u(&As[0][lrow * SROW + lc]);
    const uint32_t sb = s2u(&Bs[0][lrow * SROW + lc]);

    // -------- ldmatrix base addresses (bytes)
    // A: row = warp_m*64 + mi*16 + (lane&15), col = kh*16 + (lane>>4)*8
    const uint32_t uA = s2u(As[0]) +
        (((warp_m * 64 + (lane & 15)) * SROW + (lane >> 4) * 8) * 2);
    // B: row = warp_n*32 + nb*16 + ((lane>>4)&1)*8 + (lane&7), col = kh*16 + ((lane>>3)&1)*8
    const uint32_t uB = s2u(Bs[0]) +
        (((warp_n * 32 + ((lane >> 4) & 1) * 8 + (lane & 7)) * SROW +
          ((lane >> 3) & 1) * 8) * 2);

    float c[4][4][4];
    #pragma unroll
    for (int i = 0; i < 4; i++)
        #pragma unroll
        for (int j = 0; j < 4; j++)
            #pragma unroll
            for (int e = 0; e < 4; e++) c[i][j][e] = 0.f;

    // prologue: stage kt=0 into buf 0
    {
        CPA16(sa,                    ga);
        CPA16(sa + 64 * SROW * 2,    ga + (size_t)64 * KC);
        CPA16(sb,                    gb);
        CPA16(sb + 64 * SROW * 2,    gb + (size_t)64 * KC);
        asm volatile("cp.async.commit_group;");
    }

    const int NKT = KC / 32;  // 48
    for (int kt = 0; kt < NKT; kt++) {
        const uint32_t cbo = (kt & 1) ? SBUF : 0;   // current buffer byte offset
        if (kt + 1 < NKT) {
            const uint32_t nbo = ((kt + 1) & 1) ? SBUF : 0;
            const size_t go = (size_t)(kt + 1) * 32;
            CPA16(sa + nbo,                 ga + go);
            CPA16(sa + nbo + 64 * SROW * 2, ga + (size_t)64 * KC + go);
            CPA16(sb + nbo,                 gb + go);
            CPA16(sb + nbo + 64 * SROW * 2, gb + (size_t)64 * KC + go);
            asm volatile("cp.async.commit_group;");
            asm volatile("cp.async.wait_group 1;");
        } else {
            asm volatile("cp.async.wait_group 0;");
        }
        __syncthreads();

        #pragma unroll
        for (int kh = 0; kh < 2; kh++) {
            const uint32_t ko = kh * 16 * 2;  // 16 halves = 32 bytes
            uint32_t a[4][4], b[2][4];
            #pragma unroll
            for (int mi = 0; mi < 4; mi++)
                LDSM4(a[mi][0], a[mi][1], a[mi][2], a[mi][3],
                      uA + cbo + ko + mi * 16 * SROW * 2);
            #pragma unroll
            for (int nb = 0; nb < 2; nb++)
                LDSM4(b[nb][0], b[nb][1], b[nb][2], b[nb][3],
                      uB + cbo + ko + nb * 16 * SROW * 2);
            #pragma unroll
            for (int mi = 0; mi < 4; mi++) {
                MMA16816(c[mi][0], a[mi][0], a[mi][1], a[mi][2], a[mi][3], b[0][0], b[0][1]);
                MMA16816(c[mi][1], a[mi][0], a[mi][1], a[mi][2], a[mi][3], b[0][2], b[0][3]);
                MMA16816(c[mi][2], a[mi][0], a[mi][1], a[mi][2], a[mi][3], b[1][0], b[1][1]);
                MMA16816(c[mi][3], a[mi][0], a[mi][1], a[mi][2], a[mi][3], b[1][2], b[1][3]);
            }
        }
        __syncthreads();
    }

    // -------- epilogue: fp32 frags -> scratch
    const int mrow0 = warp_m * 64 + (lane >> 2);
    const int ncol0 = vbase + warp_n * 32 + (lane & 3) * 2;
    #pragma unroll
    for (int mi = 0; mi < 4; mi++) {
        #pragma unroll
        for (int ni = 0; ni < 4; ni++) {
            float* p0 = &C[(size_t)(mrow0 + mi * 16)     * VOCAB + ncol0 + ni * 8];
            float* p1 = &C[(size_t)(mrow0 + mi * 16 + 8) * VOCAB + ncol0 + ni * 8];
            *(float2*)p0 = make_float2(c[mi][ni][0], c[mi][ni][1]);
            *(float2*)p1 = make_float2(c[mi][ni][2], c[mi][ni][3]);
        }
    }
}

// ---------------------------------------------------------------------------
// Stage 3: broadcast add.  Block = (b=blockIdx.z, 32 t's at blockIdx.y*32,
// all 64 u's, 128-v chunk at blockIdx.x*128).  pred+bias cached in SMEM.
// L2 read traffic ~25 MB (was ~512 MB).  Streaming stores.
// ---------------------------------------------------------------------------
__device__ __forceinline__ void stcs(float4* p, float4 v) {
    asm volatile("st.global.cs.v4.f32 [%0], {%1,%2,%3,%4};"
                 :: "l"(p), "f"(v.x), "f"(v.y), "f"(v.z), "f"(v.w));
}

__global__ __launch_bounds__(256)
void add_kernel(const float* __restrict__ bias, float* __restrict__ out) {
    __shared__ float ps[64][128];     // pred + bias, this v-chunk, all u

    const int tid   = threadIdx.x;
    const int b     = blockIdx.z;
    const int tbase = blockIdx.y * 32;
    const int vbase = blockIdx.x * 128;

    // load pred chunk + bias into SMEM
    const float4* pr = (const float4*)(g_pred + (size_t)b * NU * VOCAB + vbase);
    const float4* bi = (const float4*)(bias + vbase);
    #pragma unroll
    for (int i = 0; i < 8; i++) {
        int e = tid + i * 256;
        int u = e >> 5, cc = e & 31;                 // 32 float4 per row
        float4 p = pr[(size_t)u * (VOCAB / 4) + cc];
        float4 bv = bi[cc];
        ((float4*)ps[u])[cc] =
            make_float4(p.x + bv.x, p.y + bv.y, p.z + bv.z, p.w + bv.w);
    }
    __syncthreads();

    const int w    = tid >> 5;
    const int lane = tid & 31;
    const float4* eb = (const float4*)(g_enc + (size_t)(b * NT + tbase) * VOCAB + vbase);
    float4* ob = (float4*)(out + ((size_t)(b * NT + tbase) * NU) * VOCAB + vbase);

    for (int t = 0; t < 32; t++) {
        float4 e = eb[(size_t)t * (VOCAB / 4) + lane];
        #pragma unroll
        for (int j = 0; j < 8; j++) {
            int u = w * 8 + j;
            float4 p = ((float4*)ps[u])[lane];
            stcs(&ob[((size_t)t * NU + u) * (VOCAB / 4) + lane],
                 make_float4(e.x + p.x, e.y + p.y, e.z + p.z, e.w + p.w));
        }
    }
}

// ---------------------------------------------------------------------------
extern "C" void kernel_launch(void* const* d_in, const int* in_sizes, int n_in,
                              void* d_out, int out_size) {
    const float* enc  = (const float*)d_in[0];   // (4,256,512)
    const float* pred = (const float*)d_in[1];   // (4,64,512)
    const float* W    = (const float*)d_in[2];   // (2048,1024)
    const float* bias = (const float*)d_in[3];   // (2048,)
    float* out = (float*)d_out;                  // (4,256,64,2048)

    convert_kernel<<<5376, 256>>>(enc, pred, W);
    gemm_kernel<<<dim3(16, 10), 256>>>();
    add_kernel<<<dim3(16, 8, 4), 256>>>(bias, out);
}

// round 4
// speedup vs baseline: 1.8605x; 1.1000x over previous
#include <cuda_runtime.h>
#include <cuda_bf16.h>
#include <cstdint>

// RNN-T joint network, 3 stages:
//  1) convert: fp32 -> bf16 (hi,lo) split images (K=1536 trick: hh+hl+lh)
//  2) gemm: mma.sync bf16 HMMA. Tile 64x128, BK=64, 3-stage cp.async,
//     SW128-swizzled smem, 320 CTAs @ occ 2 (balanced waves).
//  3) add: broadcast add, pred+bias in SMEM, streaming stores (DRAM-bound).

#define VOCAB 2048
#define KC    1536
#define NB    4
#define NT    256
#define NU    64

// -------- scratch (device globals; no allocations allowed) --------
__device__ __nv_bfloat16 g_Ac[1280 * KC];
__device__ __nv_bfloat16 g_Be[VOCAB * KC];
__device__ __nv_bfloat16 g_Bp[VOCAB * KC];
__device__ float g_enc [1024 * VOCAB];
__device__ float g_pred[ 256 * VOCAB];

// ---------------------------------------------------------------------------
// Stage 1: split-precision convert (unchanged; 7.6us measured)
// ---------------------------------------------------------------------------
__global__ __launch_bounds__(256)
void convert_kernel(const float* __restrict__ enc,
                    const float* __restrict__ pred,
                    const float* __restrict__ W) {
    int idx = blockIdx.x * 256 + threadIdx.x;

    float2 x;
    __nv_bfloat16* base;
    bool isA;
    if (idx < 262144) {
        x = ((const float2*)enc)[idx];
        int m = idx >> 8, k = (idx & 255) * 2;
        base = g_Ac + (size_t)m * KC + k;
        isA = true;
    } else if (idx < 327680) {
        int p = idx - 262144;
        x = ((const float2*)pred)[p];
        int m = 1024 + (p >> 8), k = (p & 255) * 2;
        base = g_Ac + (size_t)m * KC + k;
        isA = true;
    } else {
        int p = idx - 327680;
        x = ((const float2*)W)[p];
        int v = p >> 9, k = (p & 511) * 2;
        if (k < 512) base = g_Be + (size_t)v * KC + k;
        else         base = g_Bp + (size_t)v * KC + (k - 512);
        isA = false;
    }

    __nv_bfloat162 h, l;
    h.x = __float2bfloat16_rn(x.x);
    h.y = __float2bfloat16_rn(x.y);
    l.x = __float2bfloat16_rn(x.x - __bfloat162float(h.x));
    l.y = __float2bfloat16_rn(x.y - __bfloat162float(h.y));

    if (isA) {  // [hi | hi | lo]
        *(__nv_bfloat162*)(base)        = h;
        *(__nv_bfloat162*)(base +  512) = h;
        *(__nv_bfloat162*)(base + 1024) = l;
    } else {    // [hi | lo | hi]
        *(__nv_bfloat162*)(base)        = h;
        *(__nv_bfloat162*)(base +  512) = l;
        *(__nv_bfloat162*)(base + 1024) = h;
    }
}

// ---------------------------------------------------------------------------
// Stage 2: mma.sync bf16 GEMM.  C[m,v] = Ac[m,:] . B[v,:]  (K=1536)
// Tile 64(M) x 128(N), BK=64, 3-stage cp.async, SW128 swizzle (128B rows).
// 8 warps: warp_m = wid&1 (32 M-rows), warp_n = wid>>1 (32 N-cols).
// grid = (16 n-tiles, 20 m-tiles): my 0..15 -> enc, 16..19 -> pred.
// ---------------------------------------------------------------------------
#define BK     64
#define STAGES 3
#define A_ST   8192                   // 64 rows * 128B
#define B_ST   16384                  // 128 rows * 128B
#define ST_SZ  (A_ST + B_ST)          // 24KB per stage
#define DSMEM  (STAGES * ST_SZ)       // 72KB

__device__ __forceinline__ uint32_t s2u(const void* p) {
    return (uint32_t)__cvta_generic_to_shared(p);
}
#define CPA16(s, g) asm volatile("cp.async.cg.shared.global [%0], [%1], 16;" :: "r"(s), "l"(g))
#define LDSM4(r0,r1,r2,r3,a) asm volatile( \
    "ldmatrix.sync.aligned.m8n8.x4.shared.b16 {%0,%1,%2,%3}, [%4];" \
    : "=r"(r0),"=r"(r1),"=r"(r2),"=r"(r3) : "r"(a))
#define MMA16816(c,a0,a1,a2,a3,b0,b1) asm volatile( \
    "mma.sync.aligned.m16n8k16.row.col.f32.bf16.bf16.f32 " \
    "{%0,%1,%2,%3},{%4,%5,%6,%7},{%8,%9},{%0,%1,%2,%3};" \
    : "+f"(c[0]),"+f"(c[1]),"+f"(c[2]),"+f"(c[3]) \
    : "r"(a0),"r"(a1),"r"(a2),"r"(a3),"r"(b0),"r"(b1))

// SW128 within a 128B row: phys = row*128 + (cb ^ ((row&7)*16))
__device__ __forceinline__ uint32_t swz(uint32_t row, uint32_t cb) {
    return row * 128 + (cb ^ ((row & 7) * 16));
}

__global__ __launch_bounds__(256, 2)
void gemm_kernel() {
    extern __shared__ __align__(1024) char smem[];
    const uint32_t sb = s2u(smem);

    const int tid  = threadIdx.x;
    const int lane = tid & 31;
    const int wid  = tid >> 5;
    const int warp_m = wid & 1;     // 32 M rows
    const int warp_n = wid >> 1;    // 32 N cols

    const int my    = blockIdx.y;
    const int vbase = blockIdx.x * 128;

    int Arow;                        // base row in g_Ac
    const __nv_bfloat16* gBv;
    float* C;
    if (my < 16) { Arow = my * 64;                gBv = g_Be;
                   C = g_enc  + (size_t)(my * 64) * VOCAB + vbase; }
    else         { Arow = 1024 + (my - 16) * 64;  gBv = g_Bp;
                   C = g_pred + (size_t)((my - 16) * 64) * VOCAB + vbase; }

    const __nv_bfloat16* gA = g_Ac + (size_t)Arow * KC;
    const __nv_bfloat16* gB = gBv  + (size_t)vbase * KC;

    // cp.async fill precompute: A 512 chunks (2/thr), B 1024 chunks (4/thr)
    // chunk c: row = c>>3, j = c&7 (16B column chunk)
    const int ca0 = tid, ca1 = tid + 256;
    const int ra0 = ca0 >> 3, ja0 = (ca0 & 7) * 16;
    const int ra1 = ca1 >> 3, ja1 = (ca1 & 7) * 16;
    uint32_t sA0 = swz(ra0, ja0), sA1 = swz(ra1, ja1);
    int      rb[4], jb[4];
    uint32_t sB[4];
    #pragma unroll
    for (int i = 0; i < 4; i++) {
        int c = tid + i * 256;
        rb[i] = c >> 3; jb[i] = (c & 7) * 16;
        sB[i] = swz(rb[i], jb[i]);
    }

    // ldmatrix lane addresses (within a stage, relative)
    const int rowA = warp_m * 32 + (lane & 15);
    const uint32_t uA = swz(rowA, (lane >> 4) * 16);
    const int rowB = warp_n * 32 + ((lane >> 4) & 1) * 8 + (lane & 7);
    const uint32_t uB = swz(rowB, ((lane >> 3) & 1) * 16);

    float c[2][4][4];
    #pragma unroll
    for (int i = 0; i < 2; i++)
        #pragma unroll
        for (int j = 0; j < 4; j++)
            #pragma unroll
            for (int e = 0; e < 4; e++) c[i][j][e] = 0.f;

    auto fill = [&](int s, int koff) {
        const uint32_t ab = sb + s * ST_SZ;
        const uint32_t bb = ab + A_ST;
        CPA16(ab + sA0, gA + (size_t)ra0 * KC + koff + ja0 / 2);
        CPA16(ab + sA1, gA + (size_t)ra1 * KC + koff + ja1 / 2);
        #pragma unroll
        for (int i = 0; i < 4; i++)
            CPA16(bb + sB[i], gB + (size_t)rb[i] * KC + koff + jb[i] / 2);
        asm volatile("cp.async.commit_group;");
    };

    fill(0, 0);
    fill(1, BK);

    const int NKT = KC / BK;   // 24
    int s = 0;                 // stage of kt
    for (int kt = 0; kt < NKT; kt++) {
        if (kt < NKT - 1) asm volatile("cp.async.wait_group 1;");
        else              asm volatile("cp.async.wait_group 0;");
        __syncthreads();

        // refill the buffer freed at iter kt-1 (safe: sync above)
        if (kt + 2 < NKT) {
            int sn = s + 2; if (sn >= STAGES) sn -= STAGES;
            fill(sn, (kt + 2) * BK);
        }

        const uint32_t abase = sb + s * ST_SZ + uA;
        const uint32_t bbase = sb + s * ST_SZ + A_ST + uB;
        #pragma unroll
        for (int kk = 0; kk < 4; kk++) {
            uint32_t a[2][4], b[2][4];
            #pragma unroll
            for (int mi = 0; mi < 2; mi++)
                LDSM4(a[mi][0], a[mi][1], a[mi][2], a[mi][3],
                      (abase + mi * 2048) ^ (kk << 5));
            #pragma unroll
            for (int nb = 0; nb < 2; nb++)
                LDSM4(b[nb][0], b[nb][1], b[nb][2], b[nb][3],
                      (bbase + nb * 2048) ^ (kk << 5));
            #pragma unroll
            for (int mi = 0; mi < 2; mi++) {
                MMA16816(c[mi][0], a[mi][0], a[mi][1], a[mi][2], a[mi][3], b[0][0], b[0][1]);
                MMA16816(c[mi][1], a[mi][0], a[mi][1], a[mi][2], a[mi][3], b[0][2], b[0][3]);
                MMA16816(c[mi][2], a[mi][0], a[mi][1], a[mi][2], a[mi][3], b[1][0], b[1][1]);
                MMA16816(c[mi][3], a[mi][0], a[mi][1], a[mi][2], a[mi][3], b[1][2], b[1][3]);
            }
        }
        if (++s >= STAGES) s -= STAGES;
    }

    // epilogue: fp32 frags -> scratch
    const int mrow0 = warp_m * 32 + (lane >> 2);
    const int ncol0 = warp_n * 32 + (lane & 3) * 2;
    #pragma unroll
    for (int mi = 0; mi < 2; mi++) {
        #pragma unroll
        for (int ni = 0; ni < 4; ni++) {
            float* p0 = &C[(size_t)(mrow0 + mi * 16)     * VOCAB + ncol0 + ni * 8];
            float* p1 = &C[(size_t)(mrow0 + mi * 16 + 8) * VOCAB + ncol0 + ni * 8];
            *(float2*)p0 = make_float2(c[mi][ni][0], c[mi][ni][1]);
            *(float2*)p1 = make_float2(c[mi][ni][2], c[mi][ni][3]);
        }
    }
}

// ---------------------------------------------------------------------------
// Stage 3: broadcast add (unchanged from round 2).
// ---------------------------------------------------------------------------
__device__ __forceinline__ void stcs(float4* p, float4 v) {
    asm volatile("st.global.cs.v4.f32 [%0], {%1,%2,%3,%4};"
                 :: "l"(p), "f"(v.x), "f"(v.y), "f"(v.z), "f"(v.w));
}

__global__ __launch_bounds__(256)
void add_kernel(const float* __restrict__ bias, float* __restrict__ out) {
    __shared__ float ps[64][128];

    const int tid   = threadIdx.x;
    const int b     = blockIdx.z;
    const int tbase = blockIdx.y * 32;
    const int vbase = blockIdx.x * 128;

    const float4* pr = (const float4*)(g_pred + (size_t)b * NU * VOCAB + vbase);
    const float4* bi = (const float4*)(bias + vbase);
    #pragma unroll
    for (int i = 0; i < 8; i++) {
        int e = tid + i * 256;
        int u = e >> 5, cc = e & 31;
        float4 p = pr[(size_t)u * (VOCAB / 4) + cc];
        float4 bv = bi[cc];
        ((float4*)ps[u])[cc] =
            make_float4(p.x + bv.x, p.y + bv.y, p.z + bv.z, p.w + bv.w);
    }
    __syncthreads();

    const int w    = tid >> 5;
    const int lane = tid & 31;
    const float4* eb = (const float4*)(g_enc + (size_t)(b * NT + tbase) * VOCAB + vbase);
    float4* ob = (float4*)(out + ((size_t)(b * NT + tbase) * NU) * VOCAB + vbase);

    for (int t = 0; t < 32; t++) {
        float4 e = eb[(size_t)t * (VOCAB / 4) + lane];
        #pragma unroll
        for (int j = 0; j < 8; j++) {
            int u = w * 8 + j;
            float4 p = ((float4*)ps[u])[lane];
            stcs(&ob[((size_t)t * NU + u) * (VOCAB / 4) + lane],
                 make_float4(e.x + p.x, e.y + p.y, e.z + p.z, e.w + p.w));
        }
    }
}

// ---------------------------------------------------------------------------
extern "C" void kernel_launch(void* const* d_in, const int* in_sizes, int n_in,
                              void* d_out, int out_size) {
    const float* enc  = (const float*)d_in[0];
    const float* pred = (const float*)d_in[1];
    const float* W    = (const float*)d_in[2];
    const float* bias = (const float*)d_in[3];
    float* out = (float*)d_out;

    cudaFuncSetAttribute(gemm_kernel,
                         cudaFuncAttributeMaxDynamicSharedMemorySize, DSMEM);

    convert_kernel<<<5376, 256>>>(enc, pred, W);
    gemm_kernel<<<dim3(16, 20), 256, DSMEM>>>();
    add_kernel<<<dim3(16, 8, 4), 256>>>(bias, out);
}